// round 3
// baseline (speedup 1.0000x reference)
#include <cuda_runtime.h>
#include <cuda_bf16.h>
#include <cstdint>

// Problem constants
#define NUM_IMAGES 16384
#define NUM_EXPERTS 64
#define D_MODEL 4096

// Combine-kernel tiling
#define CHUNK 512                         // floats of d per chunk
#define NCHUNK (D_MODEL / CHUNK)          // 8
#define ROWTILES 18
#define ROWS_PER_TILE ((NUM_IMAGES + ROWTILES - 1) / ROWTILES)  // 911
#define CTHREADS 256
#define COLS4 (CHUNK / 4)                 // 128 float4 per row-chunk
#define RSTEP (CTHREADS / COLS4)          // 2 rows per inner iteration

// Scratch: per-row routing info {g0, g1, bitcast(e0), bitcast(e1)}  (256 KB)
__device__ float4 g_routes[NUM_IMAGES];

// ---------------------------------------------------------------------------
// Kernel 1: extract the (at most) 2 nonzero gate entries per row.
// One warp per row: lanes cover experts [lane] and [lane+32].
// ---------------------------------------------------------------------------
__global__ void moe_route_kernel(const float* __restrict__ gates) {
    int warp = (blockIdx.x * blockDim.x + threadIdx.x) >> 5;
    int lane = threadIdx.x & 31;
    if (warp >= NUM_IMAGES) return;

    const float* row = gates + (size_t)warp * NUM_EXPERTS;
    float v0 = row[lane];
    float v1 = row[lane + 32];

    unsigned m0 = __ballot_sync(0xffffffffu, v0 != 0.0f);
    unsigned m1 = __ballot_sync(0xffffffffu, v1 != 0.0f);
    unsigned long long mask = (unsigned long long)m0 |
                              ((unsigned long long)m1 << 32);

    int e0 = 0, e1 = 0;
    if (mask) {
        e0 = __ffsll((long long)mask) - 1;
        unsigned long long rest = mask & (mask - 1);
        e1 = rest ? (__ffsll((long long)rest) - 1) : e0;
    }
    // e0/e1 are warp-uniform: fetch their gate values via shuffles
    float a0 = __shfl_sync(0xffffffffu, v0, e0 & 31);
    float b0 = __shfl_sync(0xffffffffu, v1, e0 & 31);
    float g0 = (e0 < 32) ? a0 : b0;
    float a1 = __shfl_sync(0xffffffffu, v0, e1 & 31);
    float b1 = __shfl_sync(0xffffffffu, v1, e1 & 31);
    float g1 = (e1 < 32) ? a1 : b1;
    if (e1 == e0) g1 = 0.0f;       // degenerate (<2 nonzeros) safety
    if (mask == 0ull) { g0 = 0.0f; g1 = 0.0f; }

    if (lane == 0)
        g_routes[warp] = make_float4(g0, g1, __int_as_float(e0), __int_as_float(e1));
}

// ---------------------------------------------------------------------------
// Kernel 2: combine. Each CTA owns (d-chunk, row-tile).
//   smem: E slab [64][CHUNK] floats (128 KB) + tile routes (14.6 KB).
//   Inner loop: 2 rows per iteration, thread -> (row_sub, col4).
// ---------------------------------------------------------------------------
__global__ __launch_bounds__(CTHREADS, 1)
void moe_combine_kernel(const float* __restrict__ E, float* __restrict__ out) {
    extern __shared__ float smem[];
    float*  eslab = smem;                                   // [64][CHUNK]
    float4* rts   = (float4*)(smem + NUM_EXPERTS * CHUNK);  // [ROWS_PER_TILE]

    const int chunk = blockIdx.x % NCHUNK;
    const int tile  = blockIdx.x / NCHUNK;
    const int row0  = tile * ROWS_PER_TILE;
    const int rend  = min(row0 + ROWS_PER_TILE, NUM_IMAGES);
    const int nrows = rend - row0;
    const int tid   = threadIdx.x;

    // Stage E slab: 64 experts x CHUNK floats of this d-chunk
    const int slab_f4 = NUM_EXPERTS * COLS4;   // 8192 float4
    for (int idx = tid; idx < slab_f4; idx += CTHREADS) {
        int e = idx >> 7;          // / COLS4 (=128)
        int c = idx & (COLS4 - 1);
        float4 v = __ldg((const float4*)(E + (size_t)e * D_MODEL + chunk * CHUNK) + c);
        ((float4*)(eslab + e * CHUNK))[c] = v;
    }
    // Stage this tile's routes into smem (kills per-row L2-latency chain)
    for (int i = tid; i < nrows; i += CTHREADS)
        rts[i] = g_routes[row0 + i];
    __syncthreads();

    const int col = tid & (COLS4 - 1);   // 0..127
    const int sub = tid >> 7;            // 0..1  (row within iteration pair)

    float* outbase = out + (size_t)row0 * D_MODEL + chunk * CHUNK;

    #pragma unroll 4
    for (int r = sub; r < nrows; r += RSTEP) {
        float4 rt = rts[r];                       // warp-broadcast LDS
        int e0 = __float_as_int(rt.z);
        int e1 = __float_as_int(rt.w);
        float4 a = ((const float4*)(eslab + e0 * CHUNK))[col];
        float4 b = ((const float4*)(eslab + e1 * CHUNK))[col];
        float4 o;
        o.x = rt.x * a.x + rt.y * b.x;
        o.y = rt.x * a.y + rt.y * b.y;
        o.z = rt.x * a.z + rt.y * b.z;
        o.w = rt.x * a.w + rt.y * b.w;
        // streaming store: output is written once, never re-read
        __stcs((float4*)(outbase + (size_t)r * D_MODEL) + col, o);
    }
}

// ---------------------------------------------------------------------------
extern "C" void kernel_launch(void* const* d_in, const int* in_sizes, int n_in,
                              void* d_out, int out_size) {
    // Identify inputs by element count (defensive): E = 64*4096, gates = 16384*64
    const float* E     = (const float*)d_in[0];
    const float* gates = (const float*)d_in[1];
    if (in_sizes[0] == NUM_IMAGES * NUM_EXPERTS) {
        gates = (const float*)d_in[0];
        E     = (const float*)d_in[1];
    }
    float* out = (float*)d_out;

    // Routing: one warp per row, 8 warps per 256-thread block
    {
        int rows_per_block = 256 / 32;
        int blocks = (NUM_IMAGES + rows_per_block - 1) / rows_per_block;
        moe_route_kernel<<<blocks, 256>>>(gates);
    }

    // Combine: 8 chunks x 18 row tiles = 144 CTAs (one wave)
    {
        static int smem_set = 0;
        int smem_bytes = NUM_EXPERTS * CHUNK * (int)sizeof(float)
                       + ROWS_PER_TILE * (int)sizeof(float4);
        if (!smem_set) {
            cudaFuncSetAttribute(moe_combine_kernel,
                                 cudaFuncAttributeMaxDynamicSharedMemorySize,
                                 smem_bytes);
            smem_set = 1;
        }
        moe_combine_kernel<<<NCHUNK * ROWTILES, CTHREADS, smem_bytes>>>(E, out);
    }
}

// round 5
// speedup vs baseline: 1.3506x; 1.3506x over previous
#include <cuda_runtime.h>
#include <cuda_bf16.h>
#include <cstdint>

// Problem constants
#define NUM_IMAGES 16384
#define NUM_EXPERTS 64
#define D_MODEL 4096

// Combine-kernel tiling
#define CHUNK 512                         // floats of d per chunk
#define NCHUNK (D_MODEL / CHUNK)          // 8
#define ROWTILES 18
#define ROWS_PER_TILE ((NUM_IMAGES + ROWTILES - 1) / ROWTILES)  // 911
#define CTHREADS 512
#define COLS4 (CHUNK / 4)                 // 128 float4 per row-chunk
#define RSTEP (CTHREADS / COLS4)          // 4 rows per inner iteration

// Scratch: per-row routing info {g0, g1, bitcast(e0), bitcast(e1)}  (256 KB)
__device__ float4 g_routes[NUM_IMAGES];

// ---------------------------------------------------------------------------
// Kernel 1: extract the (at most) 2 nonzero gate entries per row.
// One warp per row: lanes cover experts [lane] and [lane+32].
// ---------------------------------------------------------------------------
__global__ void moe_route_kernel(const float* __restrict__ gates) {
    int warp = (blockIdx.x * blockDim.x + threadIdx.x) >> 5;
    int lane = threadIdx.x & 31;
    if (warp >= NUM_IMAGES) return;

    const float* row = gates + (size_t)warp * NUM_EXPERTS;
    float v0 = row[lane];
    float v1 = row[lane + 32];

    unsigned m0 = __ballot_sync(0xffffffffu, v0 != 0.0f);
    unsigned m1 = __ballot_sync(0xffffffffu, v1 != 0.0f);
    unsigned long long mask = (unsigned long long)m0 |
                              ((unsigned long long)m1 << 32);

    int e0 = 0, e1 = 0;
    if (mask) {
        e0 = __ffsll((long long)mask) - 1;
        unsigned long long rest = mask & (mask - 1);
        e1 = rest ? (__ffsll((long long)rest) - 1) : e0;
    }
    // e0/e1 are warp-uniform: fetch their gate values via shuffles
    float a0 = __shfl_sync(0xffffffffu, v0, e0 & 31);
    float b0 = __shfl_sync(0xffffffffu, v1, e0 & 31);
    float g0 = (e0 < 32) ? a0 : b0;
    float a1 = __shfl_sync(0xffffffffu, v0, e1 & 31);
    float b1 = __shfl_sync(0xffffffffu, v1, e1 & 31);
    float g1 = (e1 < 32) ? a1 : b1;
    if (e1 == e0) g1 = 0.0f;       // degenerate (<2 nonzeros) safety
    if (mask == 0ull) { g0 = 0.0f; g1 = 0.0f; }

    if (lane == 0)
        g_routes[warp] = make_float4(g0, g1, __int_as_float(e0), __int_as_float(e1));
}

// ---------------------------------------------------------------------------
// Kernel 2: combine. Each CTA owns (d-chunk, row-tile).
//   smem: E slab [64][CHUNK] floats (128 KB) + tile routes (14.6 KB).
//   512 threads = 16 warps/SM for latency hiding; 4 rows per inner iteration.
// ---------------------------------------------------------------------------
__global__ __launch_bounds__(CTHREADS, 1)
void moe_combine_kernel(const float* __restrict__ E, float* __restrict__ out) {
    extern __shared__ float smem[];
    float*  eslab = smem;                                   // [64][CHUNK]
    float4* rts   = (float4*)(smem + NUM_EXPERTS * CHUNK);  // [ROWS_PER_TILE]

    const int chunk = blockIdx.x % NCHUNK;
    const int tile  = blockIdx.x / NCHUNK;
    const int row0  = tile * ROWS_PER_TILE;
    const int rend  = min(row0 + ROWS_PER_TILE, NUM_IMAGES);
    const int nrows = rend - row0;
    const int tid   = threadIdx.x;

    // Stage E slab: 64 experts x CHUNK floats of this d-chunk
    const int slab_f4 = NUM_EXPERTS * COLS4;   // 8192 float4
    for (int idx = tid; idx < slab_f4; idx += CTHREADS) {
        int e = idx >> 7;          // / COLS4 (=128)
        int c = idx & (COLS4 - 1);
        float4 v = __ldg((const float4*)(E + (size_t)e * D_MODEL + chunk * CHUNK) + c);
        ((float4*)(eslab + e * CHUNK))[c] = v;
    }
    // Stage this tile's routes into smem (kills per-row L2-latency chain)
    for (int i = tid; i < nrows; i += CTHREADS)
        rts[i] = g_routes[row0 + i];
    __syncthreads();

    const int col = tid & (COLS4 - 1);   // 0..127
    const int sub = tid >> 7;            // 0..3  (row within iteration group)

    float* outbase = out + (size_t)row0 * D_MODEL + chunk * CHUNK;

    #pragma unroll 4
    for (int r = sub; r < nrows; r += RSTEP) {
        float4 rt = rts[r];                       // warp-broadcast LDS
        int e0 = __float_as_int(rt.z);
        int e1 = __float_as_int(rt.w);
        float4 a = ((const float4*)(eslab + e0 * CHUNK))[col];
        float4 b = ((const float4*)(eslab + e1 * CHUNK))[col];
        float4 o;
        o.x = rt.x * a.x + rt.y * b.x;
        o.y = rt.x * a.y + rt.y * b.y;
        o.z = rt.x * a.z + rt.y * b.z;
        o.w = rt.x * a.w + rt.y * b.w;
        // streaming store: output is written once, never re-read
        __stcs((float4*)(outbase + (size_t)r * D_MODEL) + col, o);
    }
}

// ---------------------------------------------------------------------------
extern "C" void kernel_launch(void* const* d_in, const int* in_sizes, int n_in,
                              void* d_out, int out_size) {
    // Identify inputs by element count (defensive): E = 64*4096, gates = 16384*64
    const float* E     = (const float*)d_in[0];
    const float* gates = (const float*)d_in[1];
    if (in_sizes[0] == NUM_IMAGES * NUM_EXPERTS) {
        gates = (const float*)d_in[0];
        E     = (const float*)d_in[1];
    }
    float* out = (float*)d_out;

    // Routing: one warp per row, 8 warps per 256-thread block
    {
        int rows_per_block = 256 / 32;
        int blocks = (NUM_IMAGES + rows_per_block - 1) / rows_per_block;
        moe_route_kernel<<<blocks, 256>>>(gates);
    }

    // Combine: 8 chunks x 18 row tiles = 144 CTAs (one wave)
    {
        static int smem_set = 0;
        int smem_bytes = NUM_EXPERTS * CHUNK * (int)sizeof(float)
                       + ROWS_PER_TILE * (int)sizeof(float4);
        if (!smem_set) {
            cudaFuncSetAttribute(moe_combine_kernel,
                                 cudaFuncAttributeMaxDynamicSharedMemorySize,
                                 smem_bytes);
            smem_set = 1;
        }
        moe_combine_kernel<<<NCHUNK * ROWTILES, CTHREADS, smem_bytes>>>(E, out);
    }
}